// round 1
// baseline (speedup 1.0000x reference)
#include <cuda_runtime.h>
#include <math.h>

#define TSTEPS 500
#define BATCH  32
#define NHID   1024
#define NPROJ  512
#define NGATE  4096   // 4*NHID

#define NB 128        // persistent blocks (<=148 SMs, 1 block/SM -> co-resident)
#define NT 1024
#define CELLS_PER_BLK (NHID / NB)   // 8
#define PROJ_PER_BLK  (NPROJ / NB)  // 4

// ---------------- scratch (static device globals: allocation-free) ----------
__device__ float g_Gx[TSTEPS * BATCH * NGATE];   // 262 MB input-side gate preacts
__device__ float g_Y0[TSTEPS * BATCH * NPROJ];   // layer0 output sequence
__device__ float g_Y1[TSTEPS * BATCH * NPROJ];   // layer1 output sequence
__device__ float g_h[BATCH * NPROJ];
__device__ float g_c[BATCH * NHID];
__device__ float g_m[BATCH * NHID];
__device__ unsigned g_bar_count;  // zero-init, self-resetting
__device__ unsigned g_bar_gen;

// ---------------- grid barrier (all NB blocks resident) ---------------------
__device__ __forceinline__ void grid_barrier() {
    __syncthreads();
    if (threadIdx.x == 0) {
        unsigned gen = ((volatile unsigned*)&g_bar_gen)[0];
        __threadfence();
        if (atomicAdd(&g_bar_count, 1u) == gridDim.x - 1u) {
            g_bar_count = 0u;
            __threadfence();
            atomicAdd(&g_bar_gen, 1u);
        } else {
            while (((volatile unsigned*)&g_bar_gen)[0] == gen) { __nanosleep(32); }
        }
        __threadfence();
    }
    __syncthreads();
}

__device__ __forceinline__ float sigmoidf_(float x) {
    return 1.0f / (1.0f + expf(-x));
}

// ---------------- input-side GEMM: C[M][4096] = A[M,K] @ B[4096,K]^T + bias -
// M=16000 (mult of 128), N=4096, K in {240,512} (mult of 8). No edge guards.
__global__ __launch_bounds__(256, 2)
void gemm_bias_kernel(const float* __restrict__ A, int lda,
                      const float* __restrict__ B, int ldb,
                      const float* __restrict__ bias,
                      float* __restrict__ C, int K)
{
    __shared__ float As[8][128];
    __shared__ float Bs[8][128];
    const int tid  = threadIdx.x;
    const int bm   = blockIdx.y * 128;
    const int bn   = blockIdx.x * 128;
    const int lrow = tid >> 1;
    const int seg  = (tid & 1) * 4;
    const float* Ap = A + (size_t)(bm + lrow) * lda + seg;
    const float* Bp = B + (size_t)(bn + lrow) * ldb + seg;
    const int tx = tid & 15, ty = tid >> 4;

    float acc[8][8];
#pragma unroll
    for (int i = 0; i < 8; i++)
#pragma unroll
        for (int j = 0; j < 8; j++) acc[i][j] = 0.0f;

    for (int k0 = 0; k0 < K; k0 += 8) {
        float4 av = *(const float4*)(Ap + k0);
        float4 bv = *(const float4*)(Bp + k0);
        As[seg + 0][lrow] = av.x; As[seg + 1][lrow] = av.y;
        As[seg + 2][lrow] = av.z; As[seg + 3][lrow] = av.w;
        Bs[seg + 0][lrow] = bv.x; Bs[seg + 1][lrow] = bv.y;
        Bs[seg + 2][lrow] = bv.z; Bs[seg + 3][lrow] = bv.w;
        __syncthreads();
#pragma unroll
        for (int kk = 0; kk < 8; kk++) {
            float4 a0 = *(const float4*)&As[kk][ty * 8];
            float4 a1 = *(const float4*)&As[kk][ty * 8 + 4];
            float4 b0 = *(const float4*)&Bs[kk][tx * 8];
            float4 b1 = *(const float4*)&Bs[kk][tx * 8 + 4];
            float a[8] = {a0.x, a0.y, a0.z, a0.w, a1.x, a1.y, a1.z, a1.w};
            float b[8] = {b0.x, b0.y, b0.z, b0.w, b1.x, b1.y, b1.z, b1.w};
#pragma unroll
            for (int i = 0; i < 8; i++)
#pragma unroll
                for (int j = 0; j < 8; j++)
                    acc[i][j] = fmaf(a[i], b[j], acc[i][j]);
        }
        __syncthreads();
    }

#pragma unroll
    for (int i = 0; i < 8; i++) {
        int gm = bm + ty * 8 + i;
        float* Crow = C + (size_t)gm * NGATE + bn + tx * 8;
#pragma unroll
        for (int j = 0; j < 8; j++)
            Crow[j] = acc[i][j] + bias[bn + tx * 8 + j];
    }
}

// ---------------- persistent recurrent kernel (one layer, all 500 steps) ----
// smem layout (floats): h[16384] | part[32*32*33=33792] | gate[32*33=1056] | P[4096]
#define SMEM_FLOATS (16384 + 33792 + 1056 + 4096)
#define SMEM_BYTES  (SMEM_FLOATS * 4)

__global__ __launch_bounds__(NT, 1)
void lstm_recurrent_kernel(const float* __restrict__ W, int wld, int nin,
                           const float* __restrict__ P,
                           const float* __restrict__ pi,
                           const float* __restrict__ pf,
                           const float* __restrict__ po,
                           float* __restrict__ Yout)
{
    extern __shared__ float smem[];
    float* h_sh    = smem;                 // [32][512]
    float* part_sh = smem + 16384;         // [(w*32+b)*33 + r]
    float* gate_sh = part_sh + 33792;      // [row*33 + b]
    float* P_sh    = gate_sh + 1056;       // [4][1024]

    const int tid  = threadIdx.x;
    const int bid  = blockIdx.x;
    const int warp = tid >> 5;             // k-chunk index (16 floats each)
    const int lane = tid & 31;             // local gate-row index
    const int cellbase = bid * CELLS_PER_BLK;

    // recurrent weights pinned in registers: row = g*1024 + cellbase + coff
    const int g    = lane >> 3;
    const int coff = lane & 7;
    const int grow = g * NHID + cellbase + coff;
    const int kbase = warp * 16;
    float wreg[16];
#pragma unroll
    for (int i = 0; i < 16; i++)
        wreg[i] = W[(size_t)grow * wld + nin + kbase + i];

    // projection slice pinned in shared: rows [bid*4, bid*4+4)
    {
        int r = tid >> 8;                  // 0..3
        int c = (tid & 255) * 4;
        float4 v = *(const float4*)(P + (size_t)(bid * PROJ_PER_BLK + r) * NHID + c);
        *(float4*)&P_sh[r * NHID + c] = v;
    }

    // zero initial state
    for (int i = bid * NT + tid; i < BATCH * NPROJ; i += NB * NT) g_h[i] = 0.0f;
    for (int i = bid * NT + tid; i < BATCH * NHID;  i += NB * NT) g_c[i] = 0.0f;
    grid_barrier();

    for (int t = 0; t < TSTEPS; t++) {
        // stage h into shared (L2-coherent loads: written by other SMs)
#pragma unroll
        for (int i = 0; i < 4; i++) {
            int idx = (tid + i * NT) * 4;
            float4 v = __ldcg((const float4*)&g_h[idx]);
            *(float4*)&h_sh[idx] = v;
        }
        __syncthreads();

        // recurrent GEMM: partial dot over this warp's 16-wide k-chunk,
        // h_sh reads are full-warp broadcasts (all lanes same address)
#pragma unroll 1
        for (int b = 0; b < BATCH; b++) {
            const float* hb = &h_sh[b * NPROJ + kbase];
            float4 h0 = *(const float4*)(hb + 0);
            float4 h1 = *(const float4*)(hb + 4);
            float4 h2 = *(const float4*)(hb + 8);
            float4 h3 = *(const float4*)(hb + 12);
            float a0 = wreg[0]*h0.x + wreg[1]*h0.y + wreg[2]*h0.z + wreg[3]*h0.w;
            float a1 = wreg[4]*h1.x + wreg[5]*h1.y + wreg[6]*h1.z + wreg[7]*h1.w;
            float a2 = wreg[8]*h2.x + wreg[9]*h2.y + wreg[10]*h2.z + wreg[11]*h2.w;
            float a3 = wreg[12]*h3.x + wreg[13]*h3.y + wreg[14]*h3.z + wreg[15]*h3.w;
            part_sh[(warp * BATCH + b) * 33 + lane] = (a0 + a1) + (a2 + a3);
        }
        __syncthreads();

        // reduce 32 k-chunk partials + add precomputed Gx
        {
            int r = tid & 31;              // gate row (lanes coalesce Gx read)
            int b = tid >> 5;
            float s = 0.0f;
#pragma unroll
            for (int w = 0; w < 32; w++) s += part_sh[(w * BATCH + b) * 33 + r];
            int gg = r >> 3, cc = r & 7;
            int growr = gg * NHID + cellbase + cc;
            s += g_Gx[(size_t)(t * BATCH + b) * NGATE + growr];
            gate_sh[r * 33 + b] = s;
        }
        __syncthreads();

        // cell update (this block's 8 cells x 32 batches)
        if (tid < CELLS_PER_BLK * BATCH) {
            int c = tid >> 5;
            int b = tid & 31;
            int n = cellbase + c;
            float cin = gate_sh[(0 * 8 + c) * 33 + b];
            float ig  = gate_sh[(1 * 8 + c) * 33 + b];
            float fg  = gate_sh[(2 * 8 + c) * 33 + b];
            float og  = gate_sh[(3 * 8 + c) * 33 + b];
            float cx  = g_c[b * NHID + n];
            float iv  = sigmoidf_(ig + pi[n] * cx);
            float fv  = sigmoidf_(fg + pf[n] * cx);
            float cy  = fv * cx + iv * tanhf(cin);
            cy = fminf(50.0f, fmaxf(-50.0f, cy));
            float ov  = sigmoidf_(og + po[n] * cy);
            float mv  = ov * tanhf(cy);
            g_c[b * NHID + n] = cy;
            g_m[b * NHID + n] = mv;
        }
        grid_barrier();

        // projection: h[b][pr] = sum_n m[b][n] * P[pr][n], 8-way k-split
        {
            int r   = tid >> 8;            // 0..3 local proj row
            int rem = tid & 255;
            int b   = rem >> 3;
            int sub = rem & 7;
            const float* Pr = &P_sh[r * NHID];
            const float* mb = &g_m[b * NHID];
            float acc = 0.0f;
#pragma unroll 8
            for (int i = 0; i < 128; i++) {
                int k = sub + (i << 3);
                acc = fmaf(__ldcg(&mb[k]), Pr[k], acc);
            }
            acc += __shfl_down_sync(0xffffffffu, acc, 4, 8);
            acc += __shfl_down_sync(0xffffffffu, acc, 2, 8);
            acc += __shfl_down_sync(0xffffffffu, acc, 1, 8);
            if (sub == 0) {
                int pr = bid * PROJ_PER_BLK + r;
                g_h[b * NPROJ + pr] = acc;
                Yout[(size_t)(t * BATCH + b) * NPROJ + pr] = acc;
            }
        }
        grid_barrier();
    }
}

// ---------------- launch --------------------------------------------------
extern "C" void kernel_launch(void* const* d_in, const int* in_sizes, int n_in,
                              void* d_out, int out_size)
{
    const float* x = (const float*)d_in[0];
    const float* W[3]  = {(const float*)d_in[1],  (const float*)d_in[7],  (const float*)d_in[13]};
    const float* bv[3] = {(const float*)d_in[2],  (const float*)d_in[8],  (const float*)d_in[14]};
    const float* P[3]  = {(const float*)d_in[3],  (const float*)d_in[9],  (const float*)d_in[15]};
    const float* pi[3] = {(const float*)d_in[4],  (const float*)d_in[10], (const float*)d_in[16]};
    const float* pf[3] = {(const float*)d_in[5],  (const float*)d_in[11], (const float*)d_in[17]};
    const float* po[3] = {(const float*)d_in[6],  (const float*)d_in[12], (const float*)d_in[18]};

    float *Gx, *Y0, *Y1;
    cudaGetSymbolAddress((void**)&Gx, g_Gx);
    cudaGetSymbolAddress((void**)&Y0, g_Y0);
    cudaGetSymbolAddress((void**)&Y1, g_Y1);

    cudaFuncSetAttribute(lstm_recurrent_kernel,
                         cudaFuncAttributeMaxDynamicSharedMemorySize, SMEM_BYTES);

    const int nin[3] = {240, 512, 512};
    const float* Ain[3] = {x, Y0, Y1};
    float* Yout[3] = {Y0, Y1, (float*)d_out};

    dim3 ggrid(NGATE / 128, (TSTEPS * BATCH) / 128);
    for (int l = 0; l < 3; l++) {
        gemm_bias_kernel<<<ggrid, 256>>>(Ain[l], nin[l], W[l], nin[l] + NPROJ,
                                         bv[l], Gx, nin[l]);
        lstm_recurrent_kernel<<<NB, NT, SMEM_BYTES>>>(W[l], nin[l] + NPROJ, nin[l],
                                                      P[l], pi[l], pf[l], po[l],
                                                      Yout[l]);
    }
}

// round 4
// speedup vs baseline: 1.2509x; 1.2509x over previous
#include <cuda_runtime.h>
#include <math.h>

#define TSTEPS 500
#define BATCH  32
#define NHID   1024
#define NPROJ  512
#define NGATE  4096

#define NB 128          // persistent blocks, 1/SM
#define RT 512          // threads in recurrent kernel

// ---------------- scratch (static device globals) ---------------------------
__device__ float g_Gx[TSTEPS * BATCH * NGATE];     // [t][4096][32] transposed gate preacts
__device__ float g_M [TSTEPS * BATCH * NHID];      // [t][b][1024] all m_t
__device__ float g_R [NGATE * NHID];               // fused recurrent matrix Wh@P
__device__ float g_Y0[TSTEPS * BATCH * NPROJ];
__device__ float g_Y1[TSTEPS * BATCH * NPROJ];
__device__ unsigned g_bar_count;
__device__ unsigned g_bar_gen;

// ---------------- f32x2 helpers ---------------------------------------------
__device__ __forceinline__ unsigned long long pack2(float lo, float hi) {
    unsigned long long r;
    asm("mov.b64 %0, {%1,%2};" : "=l"(r) : "f"(lo), "f"(hi));
    return r;
}
__device__ __forceinline__ void fma2(unsigned long long& acc,
                                     unsigned long long a, unsigned long long b) {
    asm("fma.rn.f32x2 %0, %1, %2, %0;" : "+l"(acc) : "l"(a), "l"(b));
}
__device__ __forceinline__ float2 unpack2(unsigned long long v) {
    float2 f;
    asm("mov.b64 {%0,%1}, %2;" : "=f"(f.x), "=f"(f.y) : "l"(v));
    return f;
}

// ---------------- grid barrier ----------------------------------------------
__device__ __forceinline__ void grid_barrier() {
    __syncthreads();
    if (threadIdx.x == 0) {
        unsigned gen = ((volatile unsigned*)&g_bar_gen)[0];
        __threadfence();
        if (atomicAdd(&g_bar_count, 1u) == gridDim.x - 1u) {
            g_bar_count = 0u;
            __threadfence();
            atomicAdd(&g_bar_gen, 1u);
        } else {
            unsigned cur;
            do {
                __nanosleep(64);
                asm volatile("ld.global.cg.u32 %0, [%1];" : "=r"(cur) : "l"(&g_bar_gen));
            } while (cur == gen);
        }
        __threadfence();
    }
    __syncthreads();
}

__device__ __forceinline__ float sigmoidf_(float x) {
    return 1.0f / (1.0f + expf(-x));
}

// ---------------- generic 128x128 GEMM, f32x2 inner --------------------------
// TRANSB=true : C[m][n] = sum_k A[m][k]*B[n][k]   (B row-major [N][K], ld=ldb)
// TRANSB=false: C[m][n] = sum_k A[m][k]*B[k][n]   (B row-major [K][N], ld=ldb)
// MODE=0: C[m*ldc + n] (+bias);  MODE=1: C[((m>>5)*4096 + n)*32 + (m&31)] (+bias)
template <int MODE, bool TRANSB, bool HASBIAS>
__global__ __launch_bounds__(256, 2)
void gemm_kernel(const float* __restrict__ A, int lda,
                 const float* __restrict__ B, int ldb,
                 const float* __restrict__ bias,
                 float* __restrict__ C, int ldc, int K)
{
    __shared__ float As[8][128];
    __shared__ float Bs[8][128];
    const int tid = threadIdx.x;
    const int bm = blockIdx.y * 128;
    const int bn = blockIdx.x * 128;
    const int lrow = tid >> 1;
    const int seg  = (tid & 1) * 4;
    const int tx = tid & 15, ty = tid >> 4;
    const int brow = tid >> 5;            // for TRANSB=false B fill
    const int bcol = (tid & 31) * 4;

    unsigned long long acc[8][4];
#pragma unroll
    for (int i = 0; i < 8; i++)
#pragma unroll
        for (int j = 0; j < 4; j++) acc[i][j] = 0ull;

    const float* Ap = A + (size_t)(bm + lrow) * lda + seg;

    for (int k0 = 0; k0 < K; k0 += 8) {
        float4 av = *(const float4*)(Ap + k0);
        As[seg + 0][lrow] = av.x; As[seg + 1][lrow] = av.y;
        As[seg + 2][lrow] = av.z; As[seg + 3][lrow] = av.w;
        if (TRANSB) {
            float4 bv = *(const float4*)(B + (size_t)(bn + lrow) * ldb + k0 + seg);
            Bs[seg + 0][lrow] = bv.x; Bs[seg + 1][lrow] = bv.y;
            Bs[seg + 2][lrow] = bv.z; Bs[seg + 3][lrow] = bv.w;
        } else {
            float4 bv = *(const float4*)(B + (size_t)(k0 + brow) * ldb + bn + bcol);
            *(float4*)&Bs[brow][bcol] = bv;
        }
        __syncthreads();
#pragma unroll
        for (int kk = 0; kk < 8; kk++) {
            float4 a0 = *(const float4*)&As[kk][ty * 8];
            float4 a1 = *(const float4*)&As[kk][ty * 8 + 4];
            ulonglong2 b01 = *(const ulonglong2*)&Bs[kk][tx * 8];
            ulonglong2 b23 = *(const ulonglong2*)&Bs[kk][tx * 8 + 4];
            float a[8] = {a0.x, a0.y, a0.z, a0.w, a1.x, a1.y, a1.z, a1.w};
#pragma unroll
            for (int i = 0; i < 8; i++) {
                unsigned long long as2 = pack2(a[i], a[i]);
                fma2(acc[i][0], as2, b01.x);
                fma2(acc[i][1], as2, b01.y);
                fma2(acc[i][2], as2, b23.x);
                fma2(acc[i][3], as2, b23.y);
            }
        }
        __syncthreads();
    }

#pragma unroll
    for (int i = 0; i < 8; i++) {
        int gm = bm + ty * 8 + i;
#pragma unroll
        for (int j = 0; j < 4; j++) {
            float2 v = unpack2(acc[i][j]);
            int n0 = bn + tx * 8 + j * 2;
            if (HASBIAS) { v.x += bias[n0]; v.y += bias[n0 + 1]; }
            if (MODE == 0) {
                C[(size_t)gm * ldc + n0]     = v.x;
                C[(size_t)gm * ldc + n0 + 1] = v.y;
            } else {
                size_t base = ((size_t)(gm >> 5) * NGATE + n0) * 32 + (gm & 31);
                C[base]      = v.x;
                C[base + 32] = v.y;
            }
        }
    }
}

// ---------------- persistent recurrent kernel --------------------------------
// gates_t = Gx_t + R @ m_{t-1};   c,m update;  m stored to g_M[t]
// block bid owns cells [bid*8, bid*8+8) -> gate rows {g*1024 + bid*8 + j}
#define REC_SMEM_FLOATS (32768 + 32*33 + 32*32)
#define REC_SMEM_BYTES  (REC_SMEM_FLOATS * 4)

__global__ __launch_bounds__(RT, 1)
void lstm_rec_kernel(const float* __restrict__ R,
                     const float* __restrict__ Gx,   // [t][4096][32]
                     const float* __restrict__ pi,
                     const float* __restrict__ pf,
                     const float* __restrict__ po,
                     float* __restrict__ Mall)       // [t][32][1024]
{
    extern __shared__ float smem[];
    float* m_sh  = smem;                  // [32][1024]
    float* gsum  = smem + 32768;          // [32 rows][33]
    float* gx_sh = gsum + 32 * 33;        // [32 rows][32]

    const int tid  = threadIdx.x;
    const int bid  = blockIdx.x;
    const int warp = tid >> 5, lane = tid & 31;
    const int half = lane >> 4, klane = lane & 15;
    const int fl   = warp * 2 + half;     // local row 0..31
    const int cellbase = bid * 8;
    const int row  = (fl >> 3) * NHID + cellbase + (fl & 7);

    // pin this thread's 64 recurrent weights as 32 f32x2 pairs
    ulonglong2 wp[16];
#pragma unroll
    for (int i = 0; i < 16; i++) {
        float4 v = *(const float4*)&R[(size_t)row * NHID + klane * 4 + i * 64];
        wp[i].x = pack2(v.x, v.y);
        wp[i].y = pack2(v.z, v.w);
    }

    // gx staging map: thread -> (local row sfl, batch pair sb)
    const int sfl = tid >> 4, sb = (tid & 15) * 2;
    const size_t gx_off = ((size_t)((sfl >> 3) * NHID + cellbase + (sfl & 7))) * 32 + sb;

    // cell state in registers (threads 0..255: cell cj, batch cb)
    const bool is_cell = (tid < 256);
    const int cj = tid >> 5, cb = tid & 31;
    float creg = 0.0f, pir = 0.0f, pfr = 0.0f, por = 0.0f;
    if (is_cell) {
        pir = pi[cellbase + cj];
        pfr = pf[cellbase + cj];
        por = po[cellbase + cj];
    }

    for (int t = 0; t < TSTEPS; t++) {
        // stage Gx tile [32 rows][32 b]
        {
            float2 v = *(const float2*)(Gx + (size_t)t * NGATE * 32 + gx_off);
            *(float2*)&gx_sh[sfl * 32 + sb] = v;
        }
        // stage m_{t-1} (written by all blocks last step; L2-coherent loads)
        if (t > 0) {
            const float* Mp = Mall + (size_t)(t - 1) * (BATCH * NHID);
#pragma unroll
            for (int u = 0; u < 16; u++) {
                int idx = (tid + u * RT) * 4;
                float4 v = __ldcg((const float4*)&Mp[idx]);
                *(float4*)&m_sh[idx] = v;
            }
        }
        __syncthreads();

        // recurrent GEMM: warp computes rows fl (2 per warp), 16-lane k-split
        if (t > 0) {
#pragma unroll 1
            for (int b = 0; b < BATCH; b++) {
                const float* mb = &m_sh[b * NHID + klane * 4];
                unsigned long long aA = 0ull, aB = 0ull;
#pragma unroll
                for (int i = 0; i < 16; i++) {
                    ulonglong2 mv = *(const ulonglong2*)(mb + i * 64);
                    fma2(aA, mv.x, wp[i].x);
                    fma2(aB, mv.y, wp[i].y);
                }
                float2 fa = unpack2(aA), fb = unpack2(aB);
                float p = (fa.x + fa.y) + (fb.x + fb.y);
#pragma unroll
                for (int off = 8; off; off >>= 1)
                    p += __shfl_down_sync(0xffffffffu, p, off, 16);
                if (klane == 0)
                    gsum[fl * 33 + b] = p + gx_sh[fl * 32 + b];
            }
        }
        __syncthreads();

        // cell update: 8 cells x 32 batches, c in registers
        if (is_cell) {
            float cin, ig, fg, og;
            if (t > 0) {
                cin = gsum[(0 * 8 + cj) * 33 + cb];
                ig  = gsum[(1 * 8 + cj) * 33 + cb];
                fg  = gsum[(2 * 8 + cj) * 33 + cb];
                og  = gsum[(3 * 8 + cj) * 33 + cb];
            } else {
                cin = gx_sh[(0 * 8 + cj) * 32 + cb];
                ig  = gx_sh[(1 * 8 + cj) * 32 + cb];
                fg  = gx_sh[(2 * 8 + cj) * 32 + cb];
                og  = gx_sh[(3 * 8 + cj) * 32 + cb];
            }
            float iv = sigmoidf_(ig + pir * creg);
            float fv = sigmoidf_(fg + pfr * creg);
            float cy = fv * creg + iv * tanhf(cin);
            cy = fminf(50.0f, fmaxf(-50.0f, cy));
            float ov = sigmoidf_(og + por * cy);
            float mv = ov * tanhf(cy);
            creg = cy;
            Mall[(size_t)t * (BATCH * NHID) + cb * NHID + cellbase + cj] = mv;
        }
        if (t + 1 < TSTEPS) grid_barrier();
    }
}

// ---------------- launch -----------------------------------------------------
extern "C" void kernel_launch(void* const* d_in, const int* in_sizes, int n_in,
                              void* d_out, int out_size)
{
    const float* x = (const float*)d_in[0];
    const float* W[3]  = {(const float*)d_in[1],  (const float*)d_in[7],  (const float*)d_in[13]};
    const float* bv[3] = {(const float*)d_in[2],  (const float*)d_in[8],  (const float*)d_in[14]};
    const float* P[3]  = {(const float*)d_in[3],  (const float*)d_in[9],  (const float*)d_in[15]};
    const float* pi[3] = {(const float*)d_in[4],  (const float*)d_in[10], (const float*)d_in[16]};
    const float* pf[3] = {(const float*)d_in[5],  (const float*)d_in[11], (const float*)d_in[17]};
    const float* po[3] = {(const float*)d_in[6],  (const float*)d_in[12], (const float*)d_in[18]};

    float *Gx, *M, *R, *Y0, *Y1;
    cudaGetSymbolAddress((void**)&Gx, g_Gx);
    cudaGetSymbolAddress((void**)&M,  g_M);
    cudaGetSymbolAddress((void**)&R,  g_R);
    cudaGetSymbolAddress((void**)&Y0, g_Y0);
    cudaGetSymbolAddress((void**)&Y1, g_Y1);

    cudaFuncSetAttribute(lstm_rec_kernel,
                         cudaFuncAttributeMaxDynamicSharedMemorySize, REC_SMEM_BYTES);

    const int nin[3] = {240, 512, 512};
    const float* Ain[3] = {x, Y0, Y1};
    float* Yout[3] = {Y0, Y1, (float*)d_out};

    const int MROWS = TSTEPS * BATCH;               // 16000

    for (int l = 0; l < 3; l++) {
        int wld = nin[l] + NPROJ;

        // R = Wh @ P : [4096 x 1024] = [4096 x 512] @ [512 x 1024]
        gemm_kernel<0, false, false><<<dim3(NHID / 128, NGATE / 128), 256>>>(
            W[l] + nin[l], wld, P[l], NHID, nullptr, R, NHID, NPROJ);

        // Gx[t][r][b] = (x W_x^T + b), transposed gate layout
        gemm_kernel<1, true, true><<<dim3(NGATE / 128, MROWS / 128), 256>>>(
            Ain[l], nin[l], W[l], wld, bv[l], Gx, 0, nin[l]);

        // recurrence -> g_M
        lstm_rec_kernel<<<NB, RT, REC_SMEM_BYTES>>>(R, Gx, pi[l], pf[l], po[l], M);

        // Y = M @ P^T : [16000 x 512]
        gemm_kernel<0, true, false><<<dim3(NPROJ / 128, MROWS / 128), 256>>>(
            M, NHID, P[l], NHID, nullptr, Yout[l], NPROJ, NHID);
    }
}